// round 1
// baseline (speedup 1.0000x reference)
#include <cuda_runtime.h>
#include <math_constants.h>

// Problem constants (fixed shapes from reference setup_inputs)
#define BB 4
#define PP 64
#define VV 32
#define DD 256

#define MARGIN 0.1f
#define L_PERM 1.0f
#define L_REG 0.1f
#define L_SIGMA 0.05f

// Scratch: cost matrix per batch (B x P x P). Device global (no allocations allowed).
__device__ float g_costs[BB * PP * PP];

// ---------------------------------------------------------------------------
// Kernel 1: one block per (b, g); 64 threads, one per p.
// costs[b,g,p] = min over valid rotations r of
//   (1/(2*min_nv)) * sum_{v<min_nv} |rot(gt_g)[v] - pred_p[v]|_1
// Polygon (cls==1): rotations r in [0, nv_g), rot(gt)[v] = gt[(r+v) % nv_g]
// Line    (cls!=1): r=0 -> gt[v];  r=1 -> gt[V-1-v] (full-V reversal)
// ---------------------------------------------------------------------------
__global__ void costs_kernel(const float* __restrict__ gt,
                             const float* __restrict__ pred,
                             const int*   __restrict__ mask,
                             const int*   __restrict__ cls)
{
    const int b = blockIdx.x / PP;
    const int g = blockIdx.x % PP;
    const int tid = threadIdx.x;          // 0..63 == p

    __shared__ float2 gt_s[VV];
    __shared__ float2 pred_s[VV][PP];     // transposed [v][p] -> conflict-free reads
    __shared__ int    nv_s[PP];

    // Load gt row for this g
    const float2* gt2 = (const float2*)(gt + ((size_t)b * PP + g) * VV * 2);
    if (tid < VV) gt_s[tid] = gt2[tid];

    // Load all pred rows of this batch, store transposed
    const float2* pr2 = (const float2*)(pred + (size_t)b * PP * VV * 2);
    for (int i = tid; i < PP * VV; i += 64) {
        int p = i / VV;
        int v = i % VV;
        pred_s[v][p] = pr2[i];
    }

    // nv[p] = number of zeros in the (sorted) mask row
    {
        const int* mrow = mask + ((size_t)b * PP + tid) * VV;
        int cnt = 0;
        #pragma unroll
        for (int v = 0; v < VV; v++) cnt += (mrow[v] == 0);
        nv_s[tid] = cnt;
    }
    __syncthreads();

    const int nvg = nv_s[g];
    const int p = tid;
    const int mn = min(nvg, nv_s[p]);
    const bool is_poly = (cls[b * PP + g] == 1);

    float best;
    if (is_poly) {
        best = CUDART_INF_F;
        for (int r = 0; r < nvg; r++) {
            float s = 0.0f;
            for (int v = 0; v < mn; v++) {
                int j = r + v;
                if (j >= nvg) j -= nvg;
                float2 a = gt_s[j];          // uniform across warp at each (r,v)
                float2 q = pred_s[v][p];
                s += fabsf(a.x - q.x) + fabsf(a.y - q.y);
            }
            best = fminf(best, s);
        }
    } else {
        float s0 = 0.0f, s1 = 0.0f;
        for (int v = 0; v < mn; v++) {
            float2 q = pred_s[v][p];
            float2 a = gt_s[v];
            float2 c = gt_s[VV - 1 - v];
            s0 += fabsf(a.x - q.x) + fabsf(a.y - q.y);
            s1 += fabsf(c.x - q.x) + fabsf(c.y - q.y);
        }
        best = fminf(s0, s1);
    }

    // mn >= 1 in practice (prob of all-ones mask row ~ 2^-32). If mn==0 this
    // yields inf/NaN, matching the reference's 0/0 semantics closely enough.
    const float cost = best / (2.0f * (float)mn);
    g_costs[((size_t)b * PP + g) * PP + p] = cost;
}

// ---------------------------------------------------------------------------
// Kernel 2: one block per batch b; 256 threads.
// Computes perm (row/col hinge maxes), broken, reg (mean of sum mu^2),
// sig (mean of 1/sigma), and the combined batch loss.
// Output layout: [batch(4), perm(4), reg(4), sig(4), broken(4)] float32.
// ---------------------------------------------------------------------------
__global__ void reduce_kernel(const float* __restrict__ mu,
                              const float* __restrict__ sigma,
                              float* __restrict__ out)
{
    const int b = blockIdx.x;
    const int tid = threadIdx.x;          // 0..255

    __shared__ float cost_s[PP * PP];     // 16 KB
    __shared__ float diag_s[PP];
    __shared__ float r_perm[256];
    __shared__ float r_reg[256];
    __shared__ float r_sig[256];

    const float* cb = g_costs + (size_t)b * PP * PP;
    for (int i = tid; i < PP * PP; i += 256) cost_s[i] = cb[i];
    __syncthreads();
    if (tid < PP) diag_s[tid] = cost_s[tid * PP + tid];
    __syncthreads();

    float perm_part = 0.0f;
    int brk = 0;

    if (tid < PP) {
        // Row g = tid: max_p of hinge with diag[g]; also broken-pair check
        const int gg = tid;
        const float dg = diag_s[gg];
        float m = 0.0f;
        for (int p = 0; p < PP; p++) {
            if (p == gg) continue;
            float c = cost_s[gg * PP + p];
            m = fmaxf(m, fmaxf(MARGIN - c + dg, 0.0f));
            if (c < dg && cost_s[p * PP + gg] < diag_s[p]) brk = 1;
        }
        perm_part = m;
    } else if (tid < 2 * PP) {
        // Column p = tid-64: max_g of hinge with diag[p]
        const int pp = tid - PP;
        const float dp = diag_s[pp];
        float m = 0.0f;
        for (int gg = 0; gg < PP; gg++) {
            if (gg == pp) continue;
            float c = cost_s[gg * PP + pp];
            m = fmaxf(m, fmaxf(MARGIN - c + dp, 0.0f));
        }
        perm_part = m;
    }

    // broken = any(brk) across the block (also acts as a barrier)
    const int broken_any = __syncthreads_or(brk);

    // reg / sig partial sums over P*D elements
    const float* mb = mu    + (size_t)b * PP * DD;
    const float* sb = sigma + (size_t)b * PP * DD;
    float sm = 0.0f, ss = 0.0f;
    for (int i = tid; i < PP * DD; i += 256) {
        float m = mb[i];
        sm += m * m;
        ss += 1.0f / sb[i];
    }

    r_perm[tid] = perm_part;
    r_reg[tid]  = sm;
    r_sig[tid]  = ss;
    __syncthreads();

    for (int s = 128; s > 0; s >>= 1) {
        if (tid < s) {
            r_perm[tid] += r_perm[tid + s];
            r_reg[tid]  += r_reg[tid + s];
            r_sig[tid]  += r_sig[tid + s];
        }
        __syncthreads();
    }

    if (tid == 0) {
        float perm = r_perm[0];
        float reg  = r_reg[0] / (float)PP;
        float sig  = r_sig[0] / (float)(PP * DD);
        float batch = L_REG * reg + L_SIGMA * sig + L_PERM * perm;
        out[b]            = batch;
        out[BB + b]       = perm;
        out[2 * BB + b]   = reg;
        out[3 * BB + b]   = sig;
        out[4 * BB + b]   = broken_any ? 1.0f : 0.0f;
    }
}

extern "C" void kernel_launch(void* const* d_in, const int* in_sizes, int n_in,
                              void* d_out, int out_size)
{
    const float* gt    = (const float*)d_in[0];   // (B,P,V,2)
    const float* pred  = (const float*)d_in[1];   // (B,P,V,2)
    const float* mu    = (const float*)d_in[2];   // (B,P,D)
    const float* sigma = (const float*)d_in[3];   // (B,P,D)
    const int*   mask  = (const int*)d_in[4];     // (B,P,V)
    const int*   cls   = (const int*)d_in[5];     // (B,P)
    float* out = (float*)d_out;

    costs_kernel<<<BB * PP, 64>>>(gt, pred, mask, cls);
    reduce_kernel<<<BB, 256>>>(mu, sigma, out);
}

// round 2
// speedup vs baseline: 1.3677x; 1.3677x over previous
#include <cuda_runtime.h>
#include <math_constants.h>

// Problem constants (fixed shapes from reference setup_inputs)
#define BB 4
#define PP 64
#define VV 32
#define DD 256

#define MARGIN 0.1f
#define L_PERM 1.0f
#define L_REG 0.1f
#define L_SIGMA 0.05f

// Scratch (device globals; no allocations allowed)
__device__ float g_costs[BB * PP * PP];   // cost matrix per batch
__device__ float g_reg[BB * PP];          // per-(b,g) sum of mu^2 over D
__device__ float g_sig[BB * PP];          // per-(b,g) sum of 1/sigma over D

// ---------------------------------------------------------------------------
// Kernel 1: one block per (b, g); 64 threads, one per p.
// Computes costs[b,g,:] AND the per-(b,g) mu^2 / 1/sigma partial sums.
// ---------------------------------------------------------------------------
__global__ void costs_kernel(const float* __restrict__ gt,
                             const float* __restrict__ pred,
                             const float* __restrict__ mu,
                             const float* __restrict__ sigma,
                             const int*   __restrict__ mask,
                             const int*   __restrict__ cls)
{
    const int b = blockIdx.x / PP;
    const int g = blockIdx.x % PP;
    const int tid = threadIdx.x;          // 0..63 == p

    __shared__ float2 gt_s[VV];
    __shared__ float2 pred_s[VV][PP];     // transposed [v][p] -> conflict-free reads
    __shared__ int    nv_s[PP];
    __shared__ float  red_s[4];

    // ---- reg/sig partials for this (b,g): 256 floats each = 64 float4 ----
    {
        const float4* m4p = (const float4*)(mu    + ((size_t)b * PP + g) * DD);
        const float4* s4p = (const float4*)(sigma + ((size_t)b * PP + g) * DD);
        float4 m4 = m4p[tid];
        float4 s4 = s4p[tid];
        float sm = m4.x * m4.x + m4.y * m4.y + m4.z * m4.z + m4.w * m4.w;
        float ss = 1.0f / s4.x + 1.0f / s4.y + 1.0f / s4.z + 1.0f / s4.w;
        // warp reduce
        #pragma unroll
        for (int o = 16; o > 0; o >>= 1) {
            sm += __shfl_down_sync(0xffffffffu, sm, o);
            ss += __shfl_down_sync(0xffffffffu, ss, o);
        }
        if ((tid & 31) == 0) {
            red_s[(tid >> 5) * 2 + 0] = sm;
            red_s[(tid >> 5) * 2 + 1] = ss;
        }
    }

    // Load gt row for this g
    const float2* gt2 = (const float2*)(gt + ((size_t)b * PP + g) * VV * 2);
    if (tid < VV) gt_s[tid] = gt2[tid];

    // Load all pred rows of this batch, store transposed
    const float2* pr2 = (const float2*)(pred + (size_t)b * PP * VV * 2);
    for (int i = tid; i < PP * VV; i += 64) {
        int p = i / VV;
        int v = i % VV;
        pred_s[v][p] = pr2[i];
    }

    // nv[p] = number of zeros in the (sorted) mask row
    {
        const int* mrow = mask + ((size_t)b * PP + tid) * VV;
        int cnt = 0;
        #pragma unroll
        for (int v = 0; v < VV; v++) cnt += (mrow[v] == 0);
        nv_s[tid] = cnt;
    }
    __syncthreads();

    if (tid == 0) {
        g_reg[b * PP + g] = red_s[0] + red_s[2];
        g_sig[b * PP + g] = red_s[1] + red_s[3];
    }

    const int nvg = nv_s[g];
    const int p = tid;
    const int mn = min(nvg, nv_s[p]);
    const bool is_poly = (cls[b * PP + g] == 1);

    float best;
    if (is_poly) {
        best = CUDART_INF_F;
        for (int r = 0; r < nvg; r++) {
            float s = 0.0f;
            for (int v = 0; v < mn; v++) {
                int j = r + v;
                if (j >= nvg) j -= nvg;
                float2 a = gt_s[j];          // uniform across warp at each (r,v)
                float2 q = pred_s[v][p];
                s += fabsf(a.x - q.x) + fabsf(a.y - q.y);
            }
            best = fminf(best, s);
        }
    } else {
        float s0 = 0.0f, s1 = 0.0f;
        for (int v = 0; v < mn; v++) {
            float2 q = pred_s[v][p];
            float2 a = gt_s[v];
            float2 c = gt_s[VV - 1 - v];
            s0 += fabsf(a.x - q.x) + fabsf(a.y - q.y);
            s1 += fabsf(c.x - q.x) + fabsf(c.y - q.y);
        }
        best = fminf(s0, s1);
    }

    const float cost = best / (2.0f * (float)mn);
    g_costs[((size_t)b * PP + g) * PP + p] = cost;
}

// ---------------------------------------------------------------------------
// Kernel 2: one block per batch b; 128 threads. Reads only L2-resident data.
// Output layout: [batch(4), perm(4), reg(4), sig(4), broken(4)] float32.
// ---------------------------------------------------------------------------
__global__ void reduce_kernel(float* __restrict__ out)
{
    const int b = blockIdx.x;
    const int tid = threadIdx.x;          // 0..127

    __shared__ float cost_s[PP * PP];     // 16 KB
    __shared__ float diag_s[PP];
    __shared__ float r_perm[128];
    __shared__ float r_reg[64];
    __shared__ float r_sig[64];

    const float4* cb4 = (const float4*)(g_costs + (size_t)b * PP * PP);
    float4* cs4 = (float4*)cost_s;
    for (int i = tid; i < PP * PP / 4; i += 128) cs4[i] = cb4[i];
    __syncthreads();
    if (tid < PP) diag_s[tid] = cost_s[tid * PP + tid];
    __syncthreads();

    float perm_part = 0.0f;
    int brk = 0;

    if (tid < PP) {
        // Row g = tid: max_p of hinge with diag[g]; also broken-pair check
        const int gg = tid;
        const float dg = diag_s[gg];
        float m = 0.0f;
        #pragma unroll 4
        for (int p = 0; p < PP; p++) {
            if (p == gg) continue;
            float c = cost_s[gg * PP + p];
            m = fmaxf(m, fmaxf(MARGIN - c + dg, 0.0f));
            if (c < dg && cost_s[p * PP + gg] < diag_s[p]) brk = 1;
        }
        perm_part = m;
    } else {
        // Column p = tid-64: max_g of hinge with diag[p]
        const int pp = tid - PP;
        const float dp = diag_s[pp];
        float m = 0.0f;
        #pragma unroll 4
        for (int gg = 0; gg < PP; gg++) {
            if (gg == pp) continue;
            float c = cost_s[gg * PP + pp];
            m = fmaxf(m, fmaxf(MARGIN - c + dp, 0.0f));
        }
        perm_part = m;
    }

    const int broken_any = __syncthreads_or(brk);

    r_perm[tid] = perm_part;
    if (tid < PP) {
        r_reg[tid] = g_reg[b * PP + tid];
        r_sig[tid] = g_sig[b * PP + tid];
    }
    __syncthreads();

    if (tid < 64) r_perm[tid] += r_perm[tid + 64];
    __syncthreads();
    for (int s = 32; s > 0; s >>= 1) {
        if (tid < s) {
            r_perm[tid] += r_perm[tid + s];
            r_reg[tid]  += r_reg[tid + s];
            r_sig[tid]  += r_sig[tid + s];
        }
        __syncthreads();
    }

    if (tid == 0) {
        float perm = r_perm[0];
        float reg  = r_reg[0] / (float)PP;
        float sig  = r_sig[0] / (float)(PP * DD);
        float batch = L_REG * reg + L_SIGMA * sig + L_PERM * perm;
        out[b]            = batch;
        out[BB + b]       = perm;
        out[2 * BB + b]   = reg;
        out[3 * BB + b]   = sig;
        out[4 * BB + b]   = broken_any ? 1.0f : 0.0f;
    }
}

extern "C" void kernel_launch(void* const* d_in, const int* in_sizes, int n_in,
                              void* d_out, int out_size)
{
    const float* gt    = (const float*)d_in[0];   // (B,P,V,2)
    const float* pred  = (const float*)d_in[1];   // (B,P,V,2)
    const float* mu    = (const float*)d_in[2];   // (B,P,D)
    const float* sigma = (const float*)d_in[3];   // (B,P,D)
    const int*   mask  = (const int*)d_in[4];     // (B,P,V)
    const int*   cls   = (const int*)d_in[5];     // (B,P)
    float* out = (float*)d_out;

    costs_kernel<<<BB * PP, 64>>>(gt, pred, mu, sigma, mask, cls);
    reduce_kernel<<<BB, 128>>>(out);
}

// round 3
// speedup vs baseline: 1.7942x; 1.3119x over previous
#include <cuda_runtime.h>
#include <math_constants.h>

#define BB 4
#define PP 64
#define VV 32
#define DD 256

#define MARGIN 0.1f
#define L_PERM 1.0f
#define L_REG 0.1f
#define L_SIGMA 0.05f

#define NBLOCKS (BB * PP)   // 256

// Device scratch (no allocations allowed)
__device__ float g_costs[BB * PP * PP];
__device__ float g_reg[BB * PP];
__device__ float g_sig[BB * PP];
__device__ unsigned int g_counter = 0;

// ---------------------------------------------------------------------------
// Fused kernel: 256 blocks x 256 threads.
// Phase 1 (all blocks): block (b,g) computes costs[b,g,:] with 4-way rotation
// split, plus per-(b,g) mu^2 / 1/sigma partials.
// Phase 2 (last block to finish): full reduction -> out.
// ---------------------------------------------------------------------------
__global__ void fused_kernel(const float* __restrict__ gt,
                             const float* __restrict__ pred,
                             const float* __restrict__ mu,
                             const float* __restrict__ sigma,
                             const int*   __restrict__ mask,
                             const int*   __restrict__ cls,
                             float* __restrict__ out)
{
    const int b = blockIdx.x >> 6;
    const int g = blockIdx.x & 63;
    const int tid = threadIdx.x;          // 0..255
    const int s = tid >> 6;               // rotation slice 0..3
    const int p = tid & 63;               // pred index

    __shared__ float2 gt_s[VV];
    __shared__ float2 pred_s[VV][PP];     // [v][p]: conflict-free (bank = p%32)
    __shared__ int    nv_s[PP];
    __shared__ float  bmin[4][PP];
    __shared__ float  red_s[16];          // 8 warps x {mu2, invsig}
    __shared__ int    is_last_s;

    // ---- reg/sig partials: one element per thread (D=256) ----
    {
        const size_t base = ((size_t)b * PP + g) * DD + tid;
        float m = mu[base];
        float sm = m * m;
        float ss = 1.0f / sigma[base];
        #pragma unroll
        for (int o = 16; o > 0; o >>= 1) {
            sm += __shfl_down_sync(0xffffffffu, sm, o);
            ss += __shfl_down_sync(0xffffffffu, ss, o);
        }
        if ((tid & 31) == 0) {
            red_s[(tid >> 5) * 2 + 0] = sm;
            red_s[(tid >> 5) * 2 + 1] = ss;
        }
    }

    // ---- load gt row for this g ----
    const float2* gt2 = (const float2*)(gt + ((size_t)b * PP + g) * VV * 2);
    if (tid < VV) gt_s[tid] = gt2[tid];

    // ---- load all pred rows of this batch, transposed ----
    const float2* pr2 = (const float2*)(pred + (size_t)b * PP * VV * 2);
    #pragma unroll
    for (int k = 0; k < PP * VV / 256; k++) {
        int i = tid + k * 256;
        pred_s[i & 31][i >> 5] = pr2[i];
    }

    // ---- nv counts (one thread per pred row) ----
    if (tid < PP) {
        const int4* mrow = (const int4*)(mask + ((size_t)b * PP + tid) * VV);
        int cnt = 0;
        #pragma unroll
        for (int k = 0; k < VV / 4; k++) {
            int4 m4 = mrow[k];
            cnt += (m4.x == 0) + (m4.y == 0) + (m4.z == 0) + (m4.w == 0);
        }
        nv_s[tid] = cnt;
    }
    __syncthreads();

    const int nvg = nv_s[g];
    const int mn  = min(nvg, nv_s[p]);
    const bool is_poly = (cls[b * PP + g] == 1);

    float best = CUDART_INF_F;
    if (is_poly) {
        for (int r = s; r < nvg; r += 4) {
            float sx = 0.0f, sy = 0.0f;
            int j = r;
            for (int v = 0; v < mn; v++) {
                float2 a = gt_s[j];            // uniform per (r,v) -> broadcast
                float2 q = pred_s[v][p];
                sx += fabsf(a.x - q.x);
                sy += fabsf(a.y - q.y);
                if (++j == nvg) j = 0;
            }
            best = fminf(best, sx + sy);
        }
    } else if (s < 2) {
        float sx = 0.0f, sy = 0.0f;
        for (int v = 0; v < mn; v++) {
            float2 q = pred_s[v][p];
            float2 a = (s == 0) ? gt_s[v] : gt_s[VV - 1 - v];
            sx += fabsf(a.x - q.x);
            sy += fabsf(a.y - q.y);
        }
        best = sx + sy;
    }
    bmin[s][p] = best;
    __syncthreads();

    if (tid < PP) {
        float c = fminf(fminf(bmin[0][tid], bmin[1][tid]),
                        fminf(bmin[2][tid], bmin[3][tid]));
        g_costs[((size_t)b * PP + g) * PP + tid] =
            c / (2.0f * (float)min(nvg, nv_s[tid]));
    }
    if (tid == 0) {
        float sm = 0.0f, ss = 0.0f;
        #pragma unroll
        for (int w = 0; w < 8; w++) { sm += red_s[w * 2]; ss += red_s[w * 2 + 1]; }
        g_reg[b * PP + g] = sm;
        g_sig[b * PP + g] = ss;
    }

    // ---- elect last block ----
    __threadfence();
    __syncthreads();
    if (tid == 0) {
        unsigned int v = atomicAdd(&g_counter, 1u);
        is_last_s = (v == NBLOCKS - 1);
    }
    __syncthreads();
    if (!is_last_s) return;

    // =========================== Phase 2 (one block) ========================
    __shared__ float diag_s[BB * PP];     // [b][i]
    __shared__ float wsum[8][3];
    __shared__ int   broken_sh[BB];

    if (tid < BB) broken_sh[tid] = 0;
    {
        const int bb = tid >> 6, ii = tid & 63;
        diag_s[tid] = g_costs[(size_t)bb * PP * PP + ii * (PP + 1)];
    }
    __syncthreads();

    const int bb = tid >> 6;
    const int ii = tid & 63;
    const float* Cb = g_costs + (size_t)bb * PP * PP;
    const float dg = diag_s[tid];

    // Row task: max_p hinge(row) + broken-pair check
    float mrow = 0.0f;
    int brk = 0;
    const float* row = Cb + ii * PP;
    #pragma unroll 16
    for (int q = 0; q < PP; q++) {
        float c = row[q];
        if (q != ii) mrow = fmaxf(mrow, fmaxf(MARGIN - c + dg, 0.0f));
        if (c < dg) {
            if (Cb[q * PP + ii] < diag_s[(bb << 6) | q]) brk = 1;
        }
    }
    // Column task: max_g hinge(col) with diag[ii]
    float mcol = 0.0f;
    #pragma unroll 16
    for (int q = 0; q < PP; q++) {
        if (q == ii) continue;
        float c = Cb[q * PP + ii];
        mcol = fmaxf(mcol, fmaxf(MARGIN - c + dg, 0.0f));
    }
    if (brk) broken_sh[bb] = 1;

    float pv = mrow + mcol;
    float rv = g_reg[tid];
    float sv = g_sig[tid];
    #pragma unroll
    for (int o = 16; o > 0; o >>= 1) {
        pv += __shfl_down_sync(0xffffffffu, pv, o);
        rv += __shfl_down_sync(0xffffffffu, rv, o);
        sv += __shfl_down_sync(0xffffffffu, sv, o);
    }
    if ((tid & 31) == 0) {
        wsum[tid >> 5][0] = pv;
        wsum[tid >> 5][1] = rv;
        wsum[tid >> 5][2] = sv;
    }
    __syncthreads();

    if (tid < BB) {
        float perm = wsum[2 * tid][0] + wsum[2 * tid + 1][0];
        float reg  = (wsum[2 * tid][1] + wsum[2 * tid + 1][1]) / (float)PP;
        float sig  = (wsum[2 * tid][2] + wsum[2 * tid + 1][2]) / (float)(PP * DD);
        float batch = L_REG * reg + L_SIGMA * sig + L_PERM * perm;
        out[tid]          = batch;
        out[BB + tid]     = perm;
        out[2 * BB + tid] = reg;
        out[3 * BB + tid] = sig;
        out[4 * BB + tid] = broken_sh[tid] ? 1.0f : 0.0f;
    }
    if (tid == 0) g_counter = 0;   // reset for next graph replay
}

extern "C" void kernel_launch(void* const* d_in, const int* in_sizes, int n_in,
                              void* d_out, int out_size)
{
    const float* gt    = (const float*)d_in[0];
    const float* pred  = (const float*)d_in[1];
    const float* mu    = (const float*)d_in[2];
    const float* sigma = (const float*)d_in[3];
    const int*   mask  = (const int*)d_in[4];
    const int*   cls   = (const int*)d_in[5];
    float* out = (float*)d_out;

    fused_kernel<<<NBLOCKS, 256>>>(gt, pred, mu, sigma, mask, cls, out);
}

// round 4
// speedup vs baseline: 1.9048x; 1.0617x over previous
#include <cuda_runtime.h>
#include <math_constants.h>

#define BB 4
#define PP 64
#define VV 32
#define DD 256

#define MARGIN 0.1f
#define L_PERM 1.0f
#define L_REG 0.1f
#define L_SIGMA 0.05f

#define NBLOCKS (BB * PP)   // 256
#define NTHREADS 512        // 8 rotation slices x 64 preds

// Device scratch (no allocations allowed)
__device__ float g_costs[BB * PP * PP];
__device__ float g_reg[BB * PP];
__device__ float g_sig[BB * PP];
__device__ unsigned int g_counter = 0;

__global__ void __launch_bounds__(NTHREADS)
fused_kernel(const float* __restrict__ gt,
             const float* __restrict__ pred,
             const float* __restrict__ mu,
             const float* __restrict__ sigma,
             const int*   __restrict__ mask,
             const int*   __restrict__ cls,
             float* __restrict__ out)
{
    const int b = blockIdx.x >> 6;
    const int g = blockIdx.x & 63;
    const int tid = threadIdx.x;          // 0..511
    const int s = tid >> 6;               // rotation slice 0..7
    const int p = tid & 63;               // pred index

    __shared__ float2 gt_s[VV];
    __shared__ float2 gt_dup[2 * VV];     // gt[k % nvg], branchless rotation index
    __shared__ float2 pred_s[VV][PP];     // [v][p]: conflict-free (bank = p%32)
    __shared__ int    nv_s[PP];
    __shared__ float  bmin[8][PP];
    __shared__ float  red_s[16];          // 8 warps x {mu2, invsig}
    __shared__ int    is_last_s;

    // ---- reg/sig partials: one element per thread for tid<256 (D=256) ----
    if (tid < DD) {
        const size_t base = ((size_t)b * PP + g) * DD + tid;
        float m = mu[base];
        float sm = m * m;
        float ss = 1.0f / sigma[base];
        #pragma unroll
        for (int o = 16; o > 0; o >>= 1) {
            sm += __shfl_down_sync(0xffffffffu, sm, o);
            ss += __shfl_down_sync(0xffffffffu, ss, o);
        }
        if ((tid & 31) == 0) {
            red_s[(tid >> 5) * 2 + 0] = sm;
            red_s[(tid >> 5) * 2 + 1] = ss;
        }
    }

    // ---- load gt row for this g ----
    const float2* gt2 = (const float2*)(gt + ((size_t)b * PP + g) * VV * 2);
    if (tid < VV) gt_s[tid] = gt2[tid];

    // ---- load all pred rows of this batch, transposed ----
    const float2* pr2 = (const float2*)(pred + (size_t)b * PP * VV * 2);
    #pragma unroll
    for (int k = 0; k < PP * VV / NTHREADS; k++) {
        int i = tid + k * NTHREADS;
        pred_s[i & 31][i >> 5] = pr2[i];
    }

    // ---- nv counts (one thread per pred row) ----
    if (tid < PP) {
        const int4* mrow = (const int4*)(mask + ((size_t)b * PP + tid) * VV);
        int cnt = 0;
        #pragma unroll
        for (int k = 0; k < VV / 4; k++) {
            int4 m4 = mrow[k];
            cnt += (m4.x == 0) + (m4.y == 0) + (m4.z == 0) + (m4.w == 0);
        }
        nv_s[tid] = cnt;
    }
    __syncthreads();

    const int nvg = nv_s[g];
    const int mn  = min(nvg, nv_s[p]);
    const bool is_poly = (cls[b * PP + g] == 1);

    // ---- build doubled gt table: gt_dup[k] = gt[k % nvg] for k < 2*VV ----
    if (tid < 2 * VV) {
        int k = tid;
        int j = (k < nvg) ? k : (k - nvg);
        if (j >= nvg) j -= nvg;            // safe even for k >= 2*nvg (unused)
        gt_dup[k] = gt_s[j];
    }
    __syncthreads();

    float best = CUDART_INF_F;
    if (is_poly) {
        for (int r = s; r < nvg; r += 8) {
            float sx = 0.0f, sy = 0.0f;
            #pragma unroll 4
            for (int v = 0; v < mn; v++) {
                float2 a = gt_dup[r + v];      // uniform per (r,v) -> broadcast
                float2 q = pred_s[v][p];
                sx += fabsf(a.x - q.x);
                sy += fabsf(a.y - q.y);
            }
            best = fminf(best, sx + sy);
        }
    } else if (s < 2) {
        float sx = 0.0f, sy = 0.0f;
        #pragma unroll 4
        for (int v = 0; v < mn; v++) {
            float2 q = pred_s[v][p];
            float2 a = (s == 0) ? gt_s[v] : gt_s[VV - 1 - v];
            sx += fabsf(a.x - q.x);
            sy += fabsf(a.y - q.y);
        }
        best = sx + sy;
    }
    bmin[s][p] = best;
    __syncthreads();

    if (tid < PP) {
        float c = CUDART_INF_F;
        #pragma unroll
        for (int k = 0; k < 8; k++) c = fminf(c, bmin[k][tid]);
        g_costs[((size_t)b * PP + g) * PP + tid] =
            c / (2.0f * (float)min(nvg, nv_s[tid]));
    }
    if (tid == 0) {
        float sm = 0.0f, ss = 0.0f;
        #pragma unroll
        for (int w = 0; w < 8; w++) { sm += red_s[w * 2]; ss += red_s[w * 2 + 1]; }
        g_reg[b * PP + g] = sm;
        g_sig[b * PP + g] = ss;
    }

    // ---- elect last block ----
    __threadfence();
    __syncthreads();
    if (tid == 0) {
        unsigned int v = atomicAdd(&g_counter, 1u);
        is_last_s = (v == NBLOCKS - 1);
    }
    __syncthreads();
    if (!is_last_s) return;

    // =========================== Phase 2 (one block) ========================
    __shared__ float diag_s[BB * PP];     // [b][i]
    __shared__ float wsum[8][3];
    __shared__ int   broken_sh[BB];

    if (tid >= 256) return;               // phase 2 uses 256 threads

    if (tid < BB) broken_sh[tid] = 0;
    {
        const int bb2 = tid >> 6, ii2 = tid & 63;
        diag_s[tid] = g_costs[(size_t)bb2 * PP * PP + ii2 * (PP + 1)];
    }
    __syncthreads();

    const int bb = tid >> 6;
    const int ii = tid & 63;
    const float* Cb = g_costs + (size_t)bb * PP * PP;
    const float dg = diag_s[tid];

    // Row task: max_p hinge(row) + broken-pair check
    float mrow = 0.0f;
    int brk = 0;
    const float* row = Cb + ii * PP;
    #pragma unroll 16
    for (int q = 0; q < PP; q++) {
        float c = row[q];
        if (q != ii) mrow = fmaxf(mrow, fmaxf(MARGIN - c + dg, 0.0f));
        if (c < dg) {
            if (Cb[q * PP + ii] < diag_s[(bb << 6) | q]) brk = 1;
        }
    }
    // Column task: max_g hinge(col) with diag[ii]
    float mcol = 0.0f;
    #pragma unroll 16
    for (int q = 0; q < PP; q++) {
        if (q == ii) continue;
        float c = Cb[q * PP + ii];
        mcol = fmaxf(mcol, fmaxf(MARGIN - c + dg, 0.0f));
    }
    if (brk) broken_sh[bb] = 1;

    float pv = mrow + mcol;
    float rv = g_reg[tid];
    float sv = g_sig[tid];
    #pragma unroll
    for (int o = 16; o > 0; o >>= 1) {
        pv += __shfl_down_sync(0xffffffffu, pv, o);
        rv += __shfl_down_sync(0xffffffffu, rv, o);
        sv += __shfl_down_sync(0xffffffffu, sv, o);
    }
    if ((tid & 31) == 0) {
        wsum[tid >> 5][0] = pv;
        wsum[tid >> 5][1] = rv;
        wsum[tid >> 5][2] = sv;
    }
    __syncthreads();

    if (tid < BB) {
        float perm = wsum[2 * tid][0] + wsum[2 * tid + 1][0];
        float reg  = (wsum[2 * tid][1] + wsum[2 * tid + 1][1]) / (float)PP;
        float sig  = (wsum[2 * tid][2] + wsum[2 * tid + 1][2]) / (float)(PP * DD);
        float batch = L_REG * reg + L_SIGMA * sig + L_PERM * perm;
        out[tid]          = batch;
        out[BB + tid]     = perm;
        out[2 * BB + tid] = reg;
        out[3 * BB + tid] = sig;
        out[4 * BB + tid] = broken_sh[tid] ? 1.0f : 0.0f;
    }
    if (tid == 0) g_counter = 0;   // reset for next graph replay
}

extern "C" void kernel_launch(void* const* d_in, const int* in_sizes, int n_in,
                              void* d_out, int out_size)
{
    const float* gt    = (const float*)d_in[0];
    const float* pred  = (const float*)d_in[1];
    const float* mu    = (const float*)d_in[2];
    const float* sigma = (const float*)d_in[3];
    const int*   mask  = (const int*)d_in[4];
    const int*   cls   = (const int*)d_in[5];
    float* out = (float*)d_out;

    fused_kernel<<<NBLOCKS, NTHREADS>>>(gt, pred, mu, sigma, mask, cls, out);
}